// round 16
// baseline (speedup 1.0000x reference)
#include <cuda_runtime.h>
#include <cuda_fp16.h>
#include <math.h>
#include <stdint.h>

// ---------------------------------------------------------------------------
// Problem constants
// ---------------------------------------------------------------------------
#define BB   2
#define CC   64
#define HH   256
#define WW   256
#define DG   8
#define CG   8
#define NOFF 144
#define NMSK 72
#define NOM  216
#define HW   65536

// scratch
__device__ float  g_offmask[(size_t)BB * NOM * HW];    // conv output (fp32 planes)
__device__ __half g_featT[(size_t)BB * HW * 128];      // [b][y][x][128c] fp16
__device__ uint4  g_wconv[48384];                      // conv W: [chunk8][half2][tap9][oc112][ci24] f16
__device__ uint4  g_weinsum[5632];                     // einsum W: [g8][oc64][ck88] f16

// warp-level HMMA
#define MMA16816(d0,d1,d2,d3,a0,a1,a2,a3,b0,b1) \
    asm volatile("mma.sync.aligned.m16n8k16.row.col.f32.f16.f16.f32 " \
        "{%0,%1,%2,%3}, {%4,%5,%6,%7}, {%8,%9}, {%0,%1,%2,%3};" \
        : "+f"(d0), "+f"(d1), "+f"(d2), "+f"(d3) \
        : "r"(a0), "r"(a1), "r"(a2), "r"(a3), "r"(b0), "r"(b1))

#define LDMATRIX_X4(r0,r1,r2,r3,addr) \
    asm volatile("ldmatrix.sync.aligned.m8n8.x4.shared.b16 {%0,%1,%2,%3}, [%4];" \
        : "=r"(r0), "=r"(r1), "=r"(r2), "=r"(r3) : "r"(addr))

#define LDMATRIX_X2(r0,r1,addr) \
    asm volatile("ldmatrix.sync.aligned.m8n8.x2.shared.b16 {%0,%1}, [%2];" \
        : "=r"(r0), "=r"(r1) : "r"(addr))

#define CP_ASYNC16(dst, src) \
    asm volatile("cp.async.cg.shared.global [%0], [%1], 16;" :: "r"(dst), "l"(src))
#define CP_ASYNC16Z(dst, src, sz) \
    asm volatile("cp.async.cg.shared.global [%0], [%1], 16, %2;" :: "r"(dst), "l"(src), "r"(sz))
#define CP_COMMIT()  asm volatile("cp.async.commit_group;" ::: "memory")
#define CP_WAIT_ALL() asm volatile("cp.async.wait_group 0;" ::: "memory")
#define CP_WAIT_1()  asm volatile("cp.async.wait_group 1;" ::: "memory")

static __device__ __forceinline__ uint32_t smem_u32(const void* p) {
    uint32_t a;
    asm("{ .reg .u64 t; cvta.to.shared.u64 t, %1; cvt.u32.u64 %0, t; }" : "=r"(a) : "l"(p));
    return a;
}

// ---------------------------------------------------------------------------
// Kernel P: merged transpose (blocks 0..4095) + weight prepack (rest).
// ---------------------------------------------------------------------------
#define NPACK_CONV (8 * 2 * 9 * 112 * 24)
#define NPACK_EIN  (8 * 64 * 88)
#define NT_BLOCKS  4096
#define NP_BLOCKS  ((NPACK_CONV + NPACK_EIN + 255) / 256)

__global__ __launch_bounds__(256, 4)
void prep_kernel(const float* __restrict__ ref, const float* __restrict__ nbr,
                 const float* __restrict__ off_w, const float* __restrict__ mask_w,
                 const float* __restrict__ weight)
{
    const int bid = blockIdx.x;
    const int tid = threadIdx.x;
    if (bid < NT_BLOCKS) {
        // ---- transpose ----
        __shared__ float t[128][33];
        const int x0 = (bid & 7) << 5;
        const int y  = (bid >> 3) & 255;
        const int b  = bid >> 11;
        #pragma unroll
        for (int i = 0; i < 16; i++) {
            int idx = tid + (i << 8);
            int c = idx >> 5;
            int x = idx & 31;
            const float* src = (c < 64) ? ref : nbr;
            t[c][x] = __ldg(src + (((size_t)b * 64 + (c & 63)) << 16) + (y << 8) + x0 + x);
        }
        __syncthreads();
        __half* dst = g_featT + ((((size_t)b << 16) + (y << 8) + x0) << 7);
        #pragma unroll
        for (int i = 0; i < 8; i++) {
            int idx = tid + (i << 8);
            int x  = idx >> 6;
            int c2 = idx & 63;
            __half2 h = __floats2half2_rn(t[2 * c2][x], t[2 * c2 + 1][x]);
            *(__half2*)(dst + (size_t)x * 128 + 2 * c2) = h;
        }
    } else {
        // ---- prepack ----
        int idx = (bid - NT_BLOCKS) * 256 + tid;
        if (idx < NPACK_CONV) {
            int cl = idx % 24;
            int r  = idx / 24;
            int ocl = r % 112;
            int r2  = r / 112;
            int tp  = r2 % 9;
            int r3  = r2 / 9;
            int h   = r3 & 1;
            int c   = r3 >> 1;
            int oc  = h * 112 + ocl;
            int ci  = c * 16 + cl;
            float v = 0.f;
            if (cl < 16) {
                if (oc < NOFF)      v = off_w[(oc * 128 + ci) * 9 + tp];
                else if (oc < NOM)  v = mask_w[((oc - NOFF) * 128 + ci) * 9 + tp];
            }
            ((__half*)g_wconv)[idx] = __float2half_rn(v);
        } else if (idx < NPACK_CONV + NPACK_EIN) {
            int j = idx - NPACK_CONV;
            int ck2 = j % 88;
            int r   = j / 88;
            int oc  = r & 63;
            int g   = r >> 6;
            float v = 0.f;
            if (ck2 < 72) {
                int k = ck2 >> 3;
                int c = ck2 & 7;
                v = weight[(oc * 64 + g * 8 + c) * 9 + k];
            }
            ((__half*)g_weinsum)[j] = __float2half_rn(v);
        }
    }
}

// ---------------------------------------------------------------------------
// Kernel 1: 3x3 conv as 9 shifted 1x1 HMMA GEMMs (unchanged from R15).
// ---------------------------------------------------------------------------
#define PATCH_SZ  8704
#define WOFF      17408
#define WSZ       48384
#define BIAS_OFF  114176
#define SMEM_TOT  114688

__global__ __launch_bounds__(256, 2)
void conv_mma_kernel(const float* __restrict__ off_b,
                     const float* __restrict__ mask_b)
{
    extern __shared__ char smem[];
    const uint32_t sb = smem_u32(smem);
    const int tid  = threadIdx.x;
    const int wid  = tid >> 5;
    const int lane = tid & 31;
    const int bz   = blockIdx.z;
    const int b    = bz >> 1;
    const int half = bz & 1;
    const int ocbase = half * 112;
    const int ty = blockIdx.y << 3;
    const int tx = blockIdx.x << 4;
    const int wm = wid & 3;
    const int wn = wid >> 2;

    const int bid  = blockIdx.x + (int)gridDim.x * (blockIdx.y + (int)gridDim.y * blockIdx.z);
    const int coff = ((bid / 148) & 1) * 4;

    float* bias_s = (float*)(smem + BIAS_OFF);
    if (tid < 112) {
        int oc = ocbase + tid;
        float bi = 0.f;
        if (oc < NOFF)     bi = off_b[oc];
        else if (oc < NOM) bi = mask_b[oc - NOFF];
        bias_s[tid] = bi;
    }

    const __half* ftb = g_featT + (((size_t)b << 16) << 7);

    int pl0 = tid % 180, h0 = tid / 180;
    int t1v = (tid < 104);
    int pl1 = (tid + 256) % 180, h1 = (tid + 256) / 180;
    int py0 = pl0 / 18, px0 = pl0 - py0 * 18;
    int py1 = pl1 / 18, px1 = pl1 - py1 * 18;
    int gy0 = ty - 1 + py0, gx0 = tx - 1 + px0;
    int gy1 = ty - 1 + py1, gx1 = tx - 1 + px1;
    bool v0 = ((unsigned)gy0 < 256u) && ((unsigned)gx0 < 256u);
    bool v1 = t1v && ((unsigned)gy1 < 256u) && ((unsigned)gx1 < 256u);
    const __half* src0 = ftb + (((size_t)(v0 ? ((gy0 << 8) + gx0) : 0)) << 7) + h0 * 8;
    const __half* src1 = ftb + (((size_t)(v1 ? ((gy1 << 8) + gx1) : 0)) << 7) + h1 * 8;
    const uint32_t d0 = (uint32_t)(pl0 * 48 + h0 * 16);
    const uint32_t d1 = (uint32_t)(pl1 * 48 + h1 * 16);
    const uint32_t z0 = v0 ? 16u : 0u;
    const uint32_t z1 = v1 ? 16u : 0u;

    float acc[2][7][4];
    #pragma unroll
    for (int mt = 0; mt < 2; mt++)
        #pragma unroll
        for (int nt = 0; nt < 7; nt++)
            #pragma unroll
            for (int q = 0; q < 4; q++) acc[mt][nt][q] = 0.f;

    const int lrow = lane & 15;
    const int lcol = lane >> 4;
    const uint32_t bro  = (uint32_t)((((lane >> 4) << 3) + (lane & 7)) * 48 + (((lane >> 3) & 1) << 4));
    const uint32_t bro6 = (uint32_t)((48 + (lane & 7)) * 48 + (((lane >> 3) & 1) << 4));

    {
        const int cc = coff;
        const uint4* wsrc = g_wconv + (size_t)(cc * 2 + half) * 3024;
        uint32_t wdst = sb + WOFF;
        #pragma unroll
        for (int i = 0; i < 12; i++) {
            int idx = tid + (i << 8);
            if (idx < 3024) CP_ASYNC16(wdst + idx * 16, (const void*)(wsrc + idx));
        }
        int cb = cc * 16;
        CP_ASYNC16Z(sb + d0, (const void*)(src0 + cb), z0);
        if (t1v) CP_ASYNC16Z(sb + d1, (const void*)(src1 + cb), z1);
        CP_COMMIT();
    }

    for (int c = 0; c < 8; c++) {
        const int s = c & 1;
        __syncthreads();
        if (c < 7) {
            const int cn = (c + 1 + coff) & 7;
            const uint4* wsrc = g_wconv + (size_t)(cn * 2 + half) * 3024;
            uint32_t wdst = sb + WOFF + (s ^ 1) * WSZ;
            #pragma unroll
            for (int i = 0; i < 12; i++) {
                int idx = tid + (i << 8);
                if (idx < 3024) CP_ASYNC16(wdst + idx * 16, (const void*)(wsrc + idx));
            }
            int cb = cn * 16;
            CP_ASYNC16Z(sb + (s ^ 1) * PATCH_SZ + d0, (const void*)(src0 + cb), z0);
            if (t1v) CP_ASYNC16Z(sb + (s ^ 1) * PATCH_SZ + d1, (const void*)(src1 + cb), z1);
            CP_COMMIT();
            CP_WAIT_1();
        } else {
            CP_WAIT_ALL();
        }
        __syncthreads();
        const uint32_t patch_s = sb + s * PATCH_SZ;
        const uint32_t wbuf = sb + WOFF + s * WSZ + (uint32_t)(wn * 2688);
        #pragma unroll 1
        for (int t = 0; t < 9; t++) {
            const int dy = t / 3;
            const int dx = t - dy * 3;
            uint32_t A[2][4];
            #pragma unroll
            for (int mt = 0; mt < 2; mt++) {
                int py = wm * 2 + mt + dy;
                uint32_t addr = patch_s + (uint32_t)((py * 18 + dx + lrow) * 48 + lcol * 16);
                LDMATRIX_X4(A[mt][0], A[mt][1], A[mt][2], A[mt][3], addr);
            }
            const uint32_t tbase = wbuf + (uint32_t)(t * 5376);
            #pragma unroll
            for (int np = 0; np < 3; np++) {
                uint32_t b00, b01, b10, b11;
                LDMATRIX_X4(b00, b01, b10, b11, tbase + (uint32_t)(np * 768) + bro);
                #pragma unroll
                for (int mt = 0; mt < 2; mt++)
                    MMA16816(acc[mt][2*np][0], acc[mt][2*np][1], acc[mt][2*np][2], acc[mt][2*np][3],
                             A[mt][0], A[mt][1], A[mt][2], A[mt][3], b00, b01);
                #pragma unroll
                for (int mt = 0; mt < 2; mt++)
                    MMA16816(acc[mt][2*np+1][0], acc[mt][2*np+1][1], acc[mt][2*np+1][2], acc[mt][2*np+1][3],
                             A[mt][0], A[mt][1], A[mt][2], A[mt][3], b10, b11);
            }
            {
                uint32_t b0, b1;
                LDMATRIX_X2(b0, b1, tbase + bro6);
                #pragma unroll
                for (int mt = 0; mt < 2; mt++)
                    MMA16816(acc[mt][6][0], acc[mt][6][1], acc[mt][6][2], acc[mt][6][3],
                             A[mt][0], A[mt][1], A[mt][2], A[mt][3], b0, b1);
            }
        }
    }

    __syncthreads();
    float* omb = g_offmask + (size_t)b * NOM * HW;
    #pragma unroll
    for (int mt = 0; mt < 2; mt++) {
        #pragma unroll
        for (int nt = 0; nt < 7; nt++) {
            int ocl0 = wn * 56 + nt * 8 + (lane & 3) * 2;
            #pragma unroll
            for (int q = 0; q < 4; q++) {
                int ocl = ocl0 + (q & 1);
                int oc  = ocbase + ocl;
                if (oc >= NOM) continue;
                int px = (wm * 2 + mt) * 16 + (lane >> 2) + ((q >> 1) << 3);
                int y = ty + (px >> 4);
                int x = tx + (px & 15);
                float val = acc[mt][nt][q] + bias_s[ocl];
                if (oc >= NOFF) val = 1.f / (1.f + __expf(-val));
                omb[(size_t)oc * HW + (y << 8) + x] = val;
            }
        }
    }
}

// ---------------------------------------------------------------------------
// Kernel 2: deformable sampling + HMMA einsum, 16x16 px tile, 512 threads.
// Double-buffered tile / Wh / offmask (cp.async 1 group ahead). occ 1.
// ---------------------------------------------------------------------------
#define S_OFF     0
#define S_SZ      45056           // 256*176
#define TILE0_OFF 45056
#define TILE_SZ   12544           // 28*28*16
#define WH0_OFF   70144
#define WH_SZ     11264
#define OM0_OFF   92672
#define OM_SZ     27648           // 27*256*4
#define SMEM_SAMP 147968

__global__ __launch_bounds__(512, 1)
void samp_einsum_kernel(const float* __restrict__ bias,
                        float* __restrict__ out)
{
    extern __shared__ char smem[];
    const uint32_t sb = smem_u32(smem);
    const int b   = blockIdx.z;
    const int ty  = blockIdx.y << 4;
    const int tx  = blockIdx.x << 4;
    const int tid = threadIdx.x;
    const int wid  = tid >> 5;
    const int lane = tid & 31;
    const int wm = wid & 7;      // 32-px group (0..7)
    const int wn = wid >> 3;     // 32-oc group (0..1)
    const int i4 = lane >> 2;
    const int k4 = lane & 3;
    const int lrow = lane & 15;
    const int lcol = lane >> 4;

    const float*  om  = g_offmask + (size_t)b * NOM * HW;
    const __half* ftb = g_featT + (((size_t)b << 16) << 7);

    if (tid < 256) {
        uint4 z = make_uint4(0, 0, 0, 0);
        *(uint4*)(smem + S_OFF + tid * 176 + 144) = z;
        *(uint4*)(smem + S_OFF + tid * 176 + 160) = z;
    }

    float acc[2][4][4];
    #pragma unroll
    for (int mt = 0; mt < 2; mt++)
        #pragma unroll
        for (int nt = 0; nt < 4; nt++)
            #pragma unroll
            for (int q = 0; q < 4; q++) acc[mt][nt][q] = 0.f;

    #define ISSUE_GROUP(gq, sbuf) do { \
        const int _cb = 64 + (gq) * 8; \
        _Pragma("unroll") \
        for (int jj = 0; jj < 2; jj++) { \
            int j = tid + jj * 512; \
            if (j < 784) { \
                int r  = j / 28; \
                int cc = j - r * 28; \
                int gy = ty - 6 + r; \
                int gx = tx - 6 + cc; \
                bool pv = ((unsigned)gy < 256u) && ((unsigned)gx < 256u); \
                const __half* src = ftb + (((size_t)(pv ? ((gy << 8) + gx) : 0)) << 7) + _cb; \
                CP_ASYNC16Z(sb + TILE0_OFF + (sbuf) * TILE_SZ + j * 16, (const void*)src, pv ? 16u : 0u); \
            } \
        } \
        _Pragma("unroll") \
        for (int jj = 0; jj < 2; jj++) { \
            int j = tid + jj * 512; \
            if (j < 704) CP_ASYNC16(sb + WH0_OFF + (sbuf) * WH_SZ + j * 16, \
                                    (const void*)(g_weinsum + (gq) * 704 + j)); \
        } \
        _Pragma("unroll") \
        for (int jj = 0; jj < 4; jj++) { \
            int j = tid + jj * 512; \
            if (j < 1728) { \
                int pj = j >> 6; \
                int rc = j & 63; \
                int r  = rc >> 2; \
                int cc = rc & 3; \
                int P  = (pj < 18) ? (18 * (gq) + pj) : (NOFF + 9 * (gq) + (pj - 18)); \
                const float* src = om + (size_t)P * HW + ((ty + r) << 8) + tx + cc * 4; \
                CP_ASYNC16(sb + OM0_OFF + (sbuf) * OM_SZ + (uint32_t)(pj * 1024 + r * 64 + cc * 16), \
                           (const void*)src); \
            } \
        } \
        CP_COMMIT(); \
    } while (0)

    ISSUE_GROUP(0, 0);

    for (int g = 0; g < 8; g++) {
        const int s = g & 1;
        const int cbase = 64 + g * 8;
        __syncthreads();

        if (g < 7) {
            ISSUE_GROUP(g + 1, s ^ 1);
            CP_WAIT_1();
        } else {
            CP_WAIT_ALL();
        }
        __syncthreads();

        // ---- merged stage 1+2: offsets (smem) -> bilinear (half2) -> S ----
        const float* om_s   = (const float*)(smem + OM0_OFF + s * OM_SZ);
        const char*  tile_s = smem + TILE0_OFF + s * TILE_SZ;
        #pragma unroll
        for (int t = 0; t < 5; t++) {
            int i = tid + t * 512;
            if (i < 2304) {
                int px = i & 255;
                int k  = i >> 8;
                int pr = px >> 4, pc = px & 15;
                int y = ty + pr, x = tx + pc;
                float dy = om_s[(2 * k) * 256 + px];
                float dx = om_s[(2 * k + 1) * 256 + px];
                float m  = om_s[(18 + k) * 256 + px];
                float sy = (float)(y - 1 + k / 3) + dy;
                float sx = (float)(x - 1 + (k - (k / 3) * 3)) + dx;
                float y0f = floorf(sy), x0f = floorf(sx);
                float wy = sy - y0f, wx = sx - x0f;
                int iy0 = (int)y0f, ix0 = (int)x0f;
                float w00 = (1.f - wy) * (1.f - wx) * m;
                float w01 = (1.f - wy) * wx * m;
                float w10 = wy * (1.f - wx) * m;
                float w11 = wy * wx * m;
                int ry = iy0 - (ty - 6);
                int rx = ix0 - (tx - 6);
                __half2 o2[4];
                if ((unsigned)ry < 27u && (unsigned)rx < 27u) {
                    const char* base = tile_s + (ry * 28 + rx) * 16;
                    uint4 c00 = *(const uint4*)(base);
                    uint4 c01 = *(const uint4*)(base + 16);
                    uint4 c10 = *(const uint4*)(base + 448);
                    uint4 c11 = *(const uint4*)(base + 464);
                    const __half2* h00 = (const __half2*)&c00;
                    const __half2* h01 = (const __half2*)&c01;
                    const __half2* h10 = (const __half2*)&c10;
                    const __half2* h11 = (const __half2*)&c11;
                    __half2 w00h = __float2half2_rn(w00);
                    __half2 w01h = __float2half2_rn(w01);
                    __half2 w10h = __float2half2_rn(w10);
                    __half2 w11h = __float2half2_rn(w11);
                    #pragma unroll
                    for (int j = 0; j < 4; j++) {
                        o2[j] = __hfma2(h00[j], w00h,
                                __hfma2(h01[j], w01h,
                                __hfma2(h10[j], w10h,
                                __hmul2(h11[j], w11h))));
                    }
                } else {
                    float a8[8];
                    #pragma unroll
                    for (int cc = 0; cc < 8; cc++) a8[cc] = 0.f;
                    float ws[4] = {w00, w01, w10, w11};
                    int cy[4] = {iy0, iy0, iy0 + 1, iy0 + 1};
                    int cx[4] = {ix0, ix0 + 1, ix0, ix0 + 1};
                    #pragma unroll
                    for (int q = 0; q < 4; q++) {
                        if ((unsigned)cy[q] < 256u && (unsigned)cx[q] < 256u) {
                            const uint4 v = *(const uint4*)(ftb + (((size_t)((cy[q] << 8) + cx[q])) << 7) + cbase);
                            const __half2* hv = (const __half2*)&v;
                            #pragma unroll
                            for (int j = 0; j < 4; j++) {
                                float2 f = __half22float2(hv[j]);
                                a8[2*j]   += ws[q] * f.x;
                                a8[2*j+1] += ws[q] * f.y;
                            }
                        }
                    }
                    #pragma unroll
                    for (int j = 0; j < 4; j++) o2[j] = __floats2half2_rn(a8[2*j], a8[2*j+1]);
                }
                *(uint4*)(smem + S_OFF + px * 176 + k * 16) = *(uint4*)o2;
            }
        }
        __syncthreads();

        // ---- HMMA einsum: acc += S x Wh[s] (K=80) ----
        const uint32_t wh_s = sb + WH0_OFF + s * WH_SZ;
        #pragma unroll
        for (int ks = 0; ks < 5; ks++) {
            uint32_t A[2][4];
            #pragma unroll
            for (int mt = 0; mt < 2; mt++) {
                uint32_t addr = sb + S_OFF +
                    (uint32_t)((wm * 32 + mt * 16 + lrow) * 176 + ks * 32 + lcol * 16);
                LDMATRIX_X4(A[mt][0], A[mt][1], A[mt][2], A[mt][3], addr);
            }
            #pragma unroll
            for (int nt = 0; nt < 4; nt++) {
                uint32_t baddr = wh_s +
                    (uint32_t)((wn * 32 + nt * 8 + i4) * 176 + ks * 32 + k4 * 4);
                uint32_t b0, b1;
                asm volatile("ld.shared.b32 %0, [%1];" : "=r"(b0) : "r"(baddr));
                asm volatile("ld.shared.b32 %0, [%1];" : "=r"(b1) : "r"(baddr + 16));
                #pragma unroll
                for (int mt = 0; mt < 2; mt++) {
                    MMA16816(acc[mt][nt][0], acc[mt][nt][1], acc[mt][nt][2], acc[mt][nt][3],
                             A[mt][0], A[mt][1], A[mt][2], A[mt][3], b0, b1);
                }
            }
        }
    }
    #undef ISSUE_GROUP

    // ---- epilogue: stage D [64 oc][256 px] to smem, coalesced stores ----
    __syncthreads();
    float* E = (float*)smem;
    #pragma unroll
    for (int mt = 0; mt < 2; mt++) {
        #pragma unroll
        for (int nt = 0; nt < 4; nt++) {
            #pragma unroll
            for (int q = 0; q < 4; q++) {
                int px = wm * 32 + mt * 16 + (lane >> 2) + ((q >> 1) << 3);
                int oc = wn * 32 + nt * 8 + ((lane & 3) << 1) + (q & 1);
                E[oc * 256 + px] = acc[mt][nt][q];
            }
        }
    }
    __syncthreads();
    #pragma unroll
    for (int j = 0; j < 8; j++) {
        int lin = tid + (j << 9);        // 0..4095
        int oc = lin >> 6;
        int u  = lin & 63;
        int px0 = u << 2;
        int pr = px0 >> 4, pc = px0 & 15;
        float bi = __ldg(bias + oc);
        float4 v = *(float4*)(E + oc * 256 + px0);
        v.x += bi; v.y += bi; v.z += bi; v.w += bi;
        *(float4*)(out + ((b * 64 + oc) << 16) + ((ty + pr) << 8) + tx + pc) = v;
    }
}

// ---------------------------------------------------------------------------
// Launch
// ---------------------------------------------------------------------------
extern "C" void kernel_launch(void* const* d_in, const int* in_sizes, int n_in,
                              void* d_out, int out_size)
{
    const float* ref    = (const float*)d_in[0];
    const float* nbr    = (const float*)d_in[1];
    const float* off_w  = (const float*)d_in[2];
    const float* off_b  = (const float*)d_in[3];
    const float* mask_w = (const float*)d_in[4];
    const float* mask_b = (const float*)d_in[5];
    const float* weight = (const float*)d_in[6];
    const float* bias   = (const float*)d_in[7];
    float* out = (float*)d_out;

    // Stage 0: merged transpose + prepack
    prep_kernel<<<NT_BLOCKS + NP_BLOCKS, 256>>>(ref, nbr, off_w, mask_w, weight);

    // Stage 1: conv
    {
        cudaFuncSetAttribute(conv_mma_kernel,
                             cudaFuncAttributeMaxDynamicSharedMemorySize, SMEM_TOT);
        dim3 grid(WW / 16, HH / 8, BB * 2);
        conv_mma_kernel<<<grid, 256, SMEM_TOT>>>(off_b, mask_b);
    }
    // Stage 2: sampling + einsum
    {
        cudaFuncSetAttribute(samp_einsum_kernel,
                             cudaFuncAttributeMaxDynamicSharedMemorySize, SMEM_SAMP);
        dim3 grid(WW / 16, HH / 16, BB);
        samp_einsum_kernel<<<grid, 512, SMEM_SAMP>>>(bias, out);
    }
}

// round 17
// speedup vs baseline: 1.0618x; 1.0618x over previous
#include <cuda_runtime.h>
#include <cuda_fp16.h>
#include <math.h>
#include <stdint.h>

// ---------------------------------------------------------------------------
// Problem constants
// ---------------------------------------------------------------------------
#define BB   2
#define CC   64
#define HH   256
#define WW   256
#define DG   8
#define CG   8
#define NOFF 144
#define NMSK 72
#define NOM  216
#define HW   65536

// scratch
__device__ float  g_offmask[(size_t)BB * NOM * HW];    // conv output (fp32 planes)
__device__ __half g_featT[(size_t)BB * HW * 128];      // [b][y][x][128c] fp16
__device__ uint4  g_wconv[48384];                      // conv W: [chunk8][half2][tap9][oc112][ci24] f16
__device__ uint4  g_weinsum[5632];                     // einsum W: [g8][oc64][ck88] f16

// warp-level HMMA
#define MMA16816(d0,d1,d2,d3,a0,a1,a2,a3,b0,b1) \
    asm volatile("mma.sync.aligned.m16n8k16.row.col.f32.f16.f16.f32 " \
        "{%0,%1,%2,%3}, {%4,%5,%6,%7}, {%8,%9}, {%0,%1,%2,%3};" \
        : "+f"(d0), "+f"(d1), "+f"(d2), "+f"(d3) \
        : "r"(a0), "r"(a1), "r"(a2), "r"(a3), "r"(b0), "r"(b1))

#define LDMATRIX_X4(r0,r1,r2,r3,addr) \
    asm volatile("ldmatrix.sync.aligned.m8n8.x4.shared.b16 {%0,%1,%2,%3}, [%4];" \
        : "=r"(r0), "=r"(r1), "=r"(r2), "=r"(r3) : "r"(addr))

#define LDMATRIX_X2(r0,r1,addr) \
    asm volatile("ldmatrix.sync.aligned.m8n8.x2.shared.b16 {%0,%1}, [%2];" \
        : "=r"(r0), "=r"(r1) : "r"(addr))

#define CP_ASYNC16(dst, src) \
    asm volatile("cp.async.cg.shared.global [%0], [%1], 16;" :: "r"(dst), "l"(src))
#define CP_ASYNC16Z(dst, src, sz) \
    asm volatile("cp.async.cg.shared.global [%0], [%1], 16, %2;" :: "r"(dst), "l"(src), "r"(sz))
#define CP_COMMIT()  asm volatile("cp.async.commit_group;" ::: "memory")
#define CP_WAIT_ALL() asm volatile("cp.async.wait_group 0;" ::: "memory")
#define CP_WAIT_1()  asm volatile("cp.async.wait_group 1;" ::: "memory")

static __device__ __forceinline__ uint32_t smem_u32(const void* p) {
    uint32_t a;
    asm("{ .reg .u64 t; cvta.to.shared.u64 t, %1; cvt.u32.u64 %0, t; }" : "=r"(a) : "l"(p));
    return a;
}

// ---------------------------------------------------------------------------
// Kernel P: merged transpose (blocks 0..4095) + weight prepack (rest).
// ---------------------------------------------------------------------------
#define NPACK_CONV (8 * 2 * 9 * 112 * 24)
#define NPACK_EIN  (8 * 64 * 88)
#define NT_BLOCKS  4096
#define NP_BLOCKS  ((NPACK_CONV + NPACK_EIN + 255) / 256)

__global__ __launch_bounds__(256, 4)
void prep_kernel(const float* __restrict__ ref, const float* __restrict__ nbr,
                 const float* __restrict__ off_w, const float* __restrict__ mask_w,
                 const float* __restrict__ weight)
{
    const int bid = blockIdx.x;
    const int tid = threadIdx.x;
    if (bid < NT_BLOCKS) {
        // ---- transpose ----
        __shared__ float t[128][33];
        const int x0 = (bid & 7) << 5;
        const int y  = (bid >> 3) & 255;
        const int b  = bid >> 11;
        #pragma unroll
        for (int i = 0; i < 16; i++) {
            int idx = tid + (i << 8);
            int c = idx >> 5;
            int x = idx & 31;
            const float* src = (c < 64) ? ref : nbr;
            t[c][x] = __ldg(src + (((size_t)b * 64 + (c & 63)) << 16) + (y << 8) + x0 + x);
        }
        __syncthreads();
        __half* dst = g_featT + ((((size_t)b << 16) + (y << 8) + x0) << 7);
        #pragma unroll
        for (int i = 0; i < 8; i++) {
            int idx = tid + (i << 8);
            int x  = idx >> 6;
            int c2 = idx & 63;
            __half2 h = __floats2half2_rn(t[2 * c2][x], t[2 * c2 + 1][x]);
            *(__half2*)(dst + (size_t)x * 128 + 2 * c2) = h;
        }
    } else {
        // ---- prepack ----
        int idx = (bid - NT_BLOCKS) * 256 + tid;
        if (idx < NPACK_CONV) {
            int cl = idx % 24;
            int r  = idx / 24;
            int ocl = r % 112;
            int r2  = r / 112;
            int tp  = r2 % 9;
            int r3  = r2 / 9;
            int h   = r3 & 1;
            int c   = r3 >> 1;
            int oc  = h * 112 + ocl;
            int ci  = c * 16 + cl;
            float v = 0.f;
            if (cl < 16) {
                if (oc < NOFF)      v = off_w[(oc * 128 + ci) * 9 + tp];
                else if (oc < NOM)  v = mask_w[((oc - NOFF) * 128 + ci) * 9 + tp];
            }
            ((__half*)g_wconv)[idx] = __float2half_rn(v);
        } else if (idx < NPACK_CONV + NPACK_EIN) {
            int j = idx - NPACK_CONV;
            int ck2 = j % 88;
            int r   = j / 88;
            int oc  = r & 63;
            int g   = r >> 6;
            float v = 0.f;
            if (ck2 < 72) {
                int k = ck2 >> 3;
                int c = ck2 & 7;
                v = weight[(oc * 64 + g * 8 + c) * 9 + k];
            }
            ((__half*)g_weinsum)[j] = __float2half_rn(v);
        }
    }
}

// ---------------------------------------------------------------------------
// Kernel 1: 3x3 conv as 9 shifted 1x1 HMMA GEMMs (R14/R15 config, unchanged).
// Block: 8x16 px tile x 112 oc. 256 threads, OCC 2.
// ---------------------------------------------------------------------------
#define PATCH_SZ  8704
#define WOFF      17408
#define WSZ       48384
#define BIAS_OFF  114176
#define SMEM_TOT  114688

__global__ __launch_bounds__(256, 2)
void conv_mma_kernel(const float* __restrict__ off_b,
                     const float* __restrict__ mask_b)
{
    extern __shared__ char smem[];
    const uint32_t sb = smem_u32(smem);
    const int tid  = threadIdx.x;
    const int wid  = tid >> 5;
    const int lane = tid & 31;
    const int bz   = blockIdx.z;
    const int b    = bz >> 1;
    const int half = bz & 1;
    const int ocbase = half * 112;
    const int ty = blockIdx.y << 3;
    const int tx = blockIdx.x << 4;
    const int wm = wid & 3;
    const int wn = wid >> 2;

    const int bid  = blockIdx.x + (int)gridDim.x * (blockIdx.y + (int)gridDim.y * blockIdx.z);
    const int coff = ((bid / 148) & 1) * 4;

    float* bias_s = (float*)(smem + BIAS_OFF);
    if (tid < 112) {
        int oc = ocbase + tid;
        float bi = 0.f;
        if (oc < NOFF)     bi = off_b[oc];
        else if (oc < NOM) bi = mask_b[oc - NOFF];
        bias_s[tid] = bi;
    }

    const __half* ftb = g_featT + (((size_t)b << 16) << 7);

    int pl0 = tid % 180, h0 = tid / 180;
    int t1v = (tid < 104);
    int pl1 = (tid + 256) % 180, h1 = (tid + 256) / 180;
    int py0 = pl0 / 18, px0 = pl0 - py0 * 18;
    int py1 = pl1 / 18, px1 = pl1 - py1 * 18;
    int gy0 = ty - 1 + py0, gx0 = tx - 1 + px0;
    int gy1 = ty - 1 + py1, gx1 = tx - 1 + px1;
    bool v0 = ((unsigned)gy0 < 256u) && ((unsigned)gx0 < 256u);
    bool v1 = t1v && ((unsigned)gy1 < 256u) && ((unsigned)gx1 < 256u);
    const __half* src0 = ftb + (((size_t)(v0 ? ((gy0 << 8) + gx0) : 0)) << 7) + h0 * 8;
    const __half* src1 = ftb + (((size_t)(v1 ? ((gy1 << 8) + gx1) : 0)) << 7) + h1 * 8;
    const uint32_t d0 = (uint32_t)(pl0 * 48 + h0 * 16);
    const uint32_t d1 = (uint32_t)(pl1 * 48 + h1 * 16);
    const uint32_t z0 = v0 ? 16u : 0u;
    const uint32_t z1 = v1 ? 16u : 0u;

    float acc[2][7][4];
    #pragma unroll
    for (int mt = 0; mt < 2; mt++)
        #pragma unroll
        for (int nt = 0; nt < 7; nt++)
            #pragma unroll
            for (int q = 0; q < 4; q++) acc[mt][nt][q] = 0.f;

    const int lrow = lane & 15;
    const int lcol = lane >> 4;
    const uint32_t bro  = (uint32_t)((((lane >> 4) << 3) + (lane & 7)) * 48 + (((lane >> 3) & 1) << 4));
    const uint32_t bro6 = (uint32_t)((48 + (lane & 7)) * 48 + (((lane >> 3) & 1) << 4));

    {
        const int cc = coff;
        const uint4* wsrc = g_wconv + (size_t)(cc * 2 + half) * 3024;
        uint32_t wdst = sb + WOFF;
        #pragma unroll
        for (int i = 0; i < 12; i++) {
            int idx = tid + (i << 8);
            if (idx < 3024) CP_ASYNC16(wdst + idx * 16, (const void*)(wsrc + idx));
        }
        int cb = cc * 16;
        CP_ASYNC16Z(sb + d0, (const void*)(src0 + cb), z0);
        if (t1v) CP_ASYNC16Z(sb + d1, (const void*)(src1 + cb), z1);
        CP_COMMIT();
    }

    for (int c = 0; c < 8; c++) {
        const int s = c & 1;
        __syncthreads();
        if (c < 7) {
            const int cn = (c + 1 + coff) & 7;
            const uint4* wsrc = g_wconv + (size_t)(cn * 2 + half) * 3024;
            uint32_t wdst = sb + WOFF + (s ^ 1) * WSZ;
            #pragma unroll
            for (int i = 0; i < 12; i++) {
                int idx = tid + (i << 8);
                if (idx < 3024) CP_ASYNC16(wdst + idx * 16, (const void*)(wsrc + idx));
            }
            int cb = cn * 16;
            CP_ASYNC16Z(sb + (s ^ 1) * PATCH_SZ + d0, (const void*)(src0 + cb), z0);
            if (t1v) CP_ASYNC16Z(sb + (s ^ 1) * PATCH_SZ + d1, (const void*)(src1 + cb), z1);
            CP_COMMIT();
            CP_WAIT_1();
        } else {
            CP_WAIT_ALL();
        }
        __syncthreads();
        const uint32_t patch_s = sb + s * PATCH_SZ;
        const uint32_t wbuf = sb + WOFF + s * WSZ + (uint32_t)(wn * 2688);
        #pragma unroll 1
        for (int t = 0; t < 9; t++) {
            const int dy = t / 3;
            const int dx = t - dy * 3;
            uint32_t A[2][4];
            #pragma unroll
            for (int mt = 0; mt < 2; mt++) {
                int py = wm * 2 + mt + dy;
                uint32_t addr = patch_s + (uint32_t)((py * 18 + dx + lrow) * 48 + lcol * 16);
                LDMATRIX_X4(A[mt][0], A[mt][1], A[mt][2], A[mt][3], addr);
            }
            const uint32_t tbase = wbuf + (uint32_t)(t * 5376);
            #pragma unroll
            for (int np = 0; np < 3; np++) {
                uint32_t b00, b01, b10, b11;
                LDMATRIX_X4(b00, b01, b10, b11, tbase + (uint32_t)(np * 768) + bro);
                #pragma unroll
                for (int mt = 0; mt < 2; mt++)
                    MMA16816(acc[mt][2*np][0], acc[mt][2*np][1], acc[mt][2*np][2], acc[mt][2*np][3],
                             A[mt][0], A[mt][1], A[mt][2], A[mt][3], b00, b01);
                #pragma unroll
                for (int mt = 0; mt < 2; mt++)
                    MMA16816(acc[mt][2*np+1][0], acc[mt][2*np+1][1], acc[mt][2*np+1][2], acc[mt][2*np+1][3],
                             A[mt][0], A[mt][1], A[mt][2], A[mt][3], b10, b11);
            }
            {
                uint32_t b0, b1;
                LDMATRIX_X2(b0, b1, tbase + bro6);
                #pragma unroll
                for (int mt = 0; mt < 2; mt++)
                    MMA16816(acc[mt][6][0], acc[mt][6][1], acc[mt][6][2], acc[mt][6][3],
                             A[mt][0], A[mt][1], A[mt][2], A[mt][3], b0, b1);
            }
        }
    }

    __syncthreads();
    float* omb = g_offmask + (size_t)b * NOM * HW;
    #pragma unroll
    for (int mt = 0; mt < 2; mt++) {
        #pragma unroll
        for (int nt = 0; nt < 7; nt++) {
            int ocl0 = wn * 56 + nt * 8 + (lane & 3) * 2;
            #pragma unroll
            for (int q = 0; q < 4; q++) {
                int ocl = ocl0 + (q & 1);
                int oc  = ocbase + ocl;
                if (oc >= NOM) continue;
                int px = (wm * 2 + mt) * 16 + (lane >> 2) + ((q >> 1) << 3);
                int y = ty + (px >> 4);
                int x = tx + (px & 15);
                float val = acc[mt][nt][q] + bias_s[ocl];
                if (oc >= NOFF) val = 1.f / (1.f + __expf(-val));
                omb[(size_t)oc * HW + (y << 8) + x] = val;
            }
        }
    }
}

// ---------------------------------------------------------------------------
// Kernel 2: deformable sampling + HMMA einsum (R15 config, unchanged).
// 8x16 px tile, 256 threads, OCC 2.
// Double-buffered: tile, Wh, offmask segments (cp.async 1 group ahead).
// ---------------------------------------------------------------------------
#define S_OFF     0
#define TILE0_OFF 22528
#define TILE_SZ   8960
#define WH0_OFF   40448
#define WH_SZ     11264
#define OM0_OFF   62976
#define OM_SZ     13824
#define SMEM_SAMP 90624

__global__ __launch_bounds__(256, 2)
void samp_einsum_kernel(const float* __restrict__ bias,
                        float* __restrict__ out)
{
    extern __shared__ char smem[];
    const uint32_t sb = smem_u32(smem);
    const int b   = blockIdx.z;
    const int ty  = blockIdx.y << 3;
    const int tx  = blockIdx.x << 4;
    const int tid = threadIdx.x;
    const int wid  = tid >> 5;
    const int lane = tid & 31;
    const int wm = wid & 3;
    const int wn = wid >> 2;
    const int i4 = lane >> 2;
    const int k4 = lane & 3;
    const int lrow = lane & 15;
    const int lcol = lane >> 4;

    const float*  om  = g_offmask + (size_t)b * NOM * HW;
    const __half* ftb = g_featT + (((size_t)b << 16) << 7);

    if (tid < 128) {
        uint4 z = make_uint4(0, 0, 0, 0);
        *(uint4*)(smem + S_OFF + tid * 176 + 144) = z;
        *(uint4*)(smem + S_OFF + tid * 176 + 160) = z;
    }

    float acc[2][4][4];
    #pragma unroll
    for (int mt = 0; mt < 2; mt++)
        #pragma unroll
        for (int nt = 0; nt < 4; nt++)
            #pragma unroll
            for (int q = 0; q < 4; q++) acc[mt][nt][q] = 0.f;

    #define ISSUE_GROUP(gq, sbuf) do { \
        const int _cb = 64 + (gq) * 8; \
        _Pragma("unroll") \
        for (int jj = 0; jj < 3; jj++) { \
            int j = tid + jj * 256; \
            if (j < 560) { \
                int r  = j / 28; \
                int cc = j - r * 28; \
                int gy = ty - 6 + r; \
                int gx = tx - 6 + cc; \
                bool pv = ((unsigned)gy < 256u) && ((unsigned)gx < 256u); \
                const __half* src = ftb + (((size_t)(pv ? ((gy << 8) + gx) : 0)) << 7) + _cb; \
                CP_ASYNC16Z(sb + TILE0_OFF + (sbuf) * TILE_SZ + j * 16, (const void*)src, pv ? 16u : 0u); \
            } \
        } \
        _Pragma("unroll") \
        for (int jj = 0; jj < 3; jj++) { \
            int j = tid + jj * 256; \
            if (j < 704) CP_ASYNC16(sb + WH0_OFF + (sbuf) * WH_SZ + j * 16, \
                                    (const void*)(g_weinsum + (gq) * 704 + j)); \
        } \
        _Pragma("unroll") \
        for (int jj = 0; jj < 4; jj++) { \
            int j = tid + jj * 256; \
            if (j < 864) { \
                int pj = j >> 5; \
                int rc = j & 31; \
                int r  = rc >> 2; \
                int cc = rc & 3; \
                int P  = (pj < 18) ? (18 * (gq) + pj) : (NOFF + 9 * (gq) + (pj - 18)); \
                const float* src = om + (size_t)P * HW + ((ty + r) << 8) + tx + cc * 4; \
                CP_ASYNC16(sb + OM0_OFF + (sbuf) * OM_SZ + (uint32_t)(pj * 512 + r * 64 + cc * 16), \
                           (const void*)src); \
            } \
        } \
        CP_COMMIT(); \
    } while (0)

    ISSUE_GROUP(0, 0);

    for (int g = 0; g < 8; g++) {
        const int s = g & 1;
        const int cbase = 64 + g * 8;
        __syncthreads();

        if (g < 7) {
            ISSUE_GROUP(g + 1, s ^ 1);
            CP_WAIT_1();
        } else {
            CP_WAIT_ALL();
        }
        __syncthreads();

        // ---- merged stage 1+2: offsets (smem) -> bilinear (half2) -> S ----
        const float* om_s   = (const float*)(smem + OM0_OFF + s * OM_SZ);
        const char*  tile_s = smem + TILE0_OFF + s * TILE_SZ;
        #pragma unroll
        for (int t = 0; t < 5; t++) {
            int i = tid + t * 256;
            if (i < 1152) {
                int px = i & 127;
                int k  = i >> 7;
                int pr = px >> 4, pc = px & 15;
                int y = ty + pr, x = tx + pc;
                float dy = om_s[(2 * k) * 128 + px];
                float dx = om_s[(2 * k + 1) * 128 + px];
                float m  = om_s[(18 + k) * 128 + px];
                float sy = (float)(y - 1 + k / 3) + dy;
                float sx = (float)(x - 1 + (k - (k / 3) * 3)) + dx;
                float y0f = floorf(sy), x0f = floorf(sx);
                float wy = sy - y0f, wx = sx - x0f;
                int iy0 = (int)y0f, ix0 = (int)x0f;
                float w00 = (1.f - wy) * (1.f - wx) * m;
                float w01 = (1.f - wy) * wx * m;
                float w10 = wy * (1.f - wx) * m;
                float w11 = wy * wx * m;
                int ry = iy0 - (ty - 6);
                int rx = ix0 - (tx - 6);
                __half2 o2[4];
                if ((unsigned)ry < 19u && (unsigned)rx < 27u) {
                    const char* base = tile_s + (ry * 28 + rx) * 16;
                    uint4 c00 = *(const uint4*)(base);
                    uint4 c01 = *(const uint4*)(base + 16);
                    uint4 c10 = *(const uint4*)(base + 448);
                    uint4 c11 = *(const uint4*)(base + 464);
                    const __half2* h00 = (const __half2*)&c00;
                    const __half2* h01 = (const __half2*)&c01;
                    const __half2* h10 = (const __half2*)&c10;
                    const __half2* h11 = (const __half2*)&c11;
                    __half2 w00h = __float2half2_rn(w00);
                    __half2 w01h = __float2half2_rn(w01);
                    __half2 w10h = __float2half2_rn(w10);
                    __half2 w11h = __float2half2_rn(w11);
                    #pragma unroll
                    for (int j = 0; j < 4; j++) {
                        o2[j] = __hfma2(h00[j], w00h,
                                __hfma2(h01[j], w01h,
                                __hfma2(h10[j], w10h,
                                __hmul2(h11[j], w11h))));
                    }
                } else {
                    float a8[8];
                    #pragma unroll
                    for (int cc = 0; cc < 8; cc++) a8[cc] = 0.f;
                    float ws[4] = {w00, w01, w10, w11};
                    int cy[4] = {iy0, iy0, iy0 + 1, iy0 + 1};
                    int cx[4] = {ix0, ix0 + 1, ix0, ix0 + 1};
                    #pragma unroll
                    for (int q = 0; q < 4; q++) {
                        if ((unsigned)cy[q] < 256u && (unsigned)cx[q] < 256u) {
                            const uint4 v = *(const uint4*)(ftb + (((size_t)((cy[q] << 8) + cx[q])) << 7) + cbase);
                            const __half2* hv = (const __half2*)&v;
                            #pragma unroll
                            for (int j = 0; j < 4; j++) {
                                float2 f = __half22float2(hv[j]);
                                a8[2*j]   += ws[q] * f.x;
                                a8[2*j+1] += ws[q] * f.y;
                            }
                        }
                    }
                    #pragma unroll
                    for (int j = 0; j < 4; j++) o2[j] = __floats2half2_rn(a8[2*j], a8[2*j+1]);
                }
                *(uint4*)(smem + S_OFF + px * 176 + k * 16) = *(uint4*)o2;
            }
        }
        __syncthreads();

        // ---- HMMA einsum: acc += S x Wh[s] (K=80) ----
        const uint32_t wh_s = sb + WH0_OFF + s * WH_SZ;
        #pragma unroll
        for (int ks = 0; ks < 5; ks++) {
            uint32_t A[2][4];
            #pragma unroll
            for (int mt = 0; mt < 2; mt++) {
                uint32_t addr = sb + S_OFF +
                    (uint32_t)((wm * 32 + mt * 16 + lrow) * 176 + ks * 32 + lcol * 16);
                LDMATRIX_X4(A[mt][0], A[mt][1], A[mt][2], A[mt][3], addr);
            }
            #pragma unroll
            for (int nt = 0; nt < 4; nt++) {
                uint32_t baddr = wh_s +
                    (uint32_t)((wn * 32 + nt * 8 + i4) * 176 + ks * 32 + k4 * 4);
                uint32_t b0, b1;
                asm volatile("ld.shared.b32 %0, [%1];" : "=r"(b0) : "r"(baddr));
                asm volatile("ld.shared.b32 %0, [%1];" : "=r"(b1) : "r"(baddr + 16));
                #pragma unroll
                for (int mt = 0; mt < 2; mt++) {
                    MMA16816(acc[mt][nt][0], acc[mt][nt][1], acc[mt][nt][2], acc[mt][nt][3],
                             A[mt][0], A[mt][1], A[mt][2], A[mt][3], b0, b1);
                }
            }
        }
    }
    #undef ISSUE_GROUP

    // ---- epilogue ----
    __syncthreads();
    float* E = (float*)smem;
    #pragma unroll
    for (int mt = 0; mt < 2; mt++) {
        #pragma unroll
        for (int nt = 0; nt < 4; nt++) {
            #pragma unroll
            for (int q = 0; q < 4; q++) {
                int px = wm * 32 + mt * 16 + (lane >> 2) + ((q >> 1) << 3);
                int oc = wn * 32 + nt * 8 + ((lane & 3) << 1) + (q & 1);
                E[oc * 128 + px] = acc[mt][nt][q];
            }
        }
    }
    __syncthreads();
    #pragma unroll
    for (int j = 0; j < 8; j++) {
        int lin = tid + (j << 8);
        int oc = lin >> 5;
        int u  = lin & 31;
        int px0 = u << 2;
        int pr = px0 >> 4, pc = px0 & 15;
        float bi = __ldg(bias + oc);
        float4 v = *(float4*)(E + oc * 128 + px0);
        v.x += bi; v.y += bi; v.z += bi; v.w += bi;
        *(float4*)(out + ((b * 64 + oc) << 16) + ((ty + pr) << 8) + tx + pc) = v;
    }
}

// ---------------------------------------------------------------------------
// Launch
// ---------------------------------------------------------------------------
extern "C" void kernel_launch(void* const* d_in, const int* in_sizes, int n_in,
                              void* d_out, int out_size)
{
    const float* ref    = (const float*)d_in[0];
    const float* nbr    = (const float*)d_in[1];
    const float* off_w  = (const float*)d_in[2];
    const float* off_b  = (const float*)d_in[3];
    const float* mask_w = (const float*)d_in[4];
    const float* mask_b = (const float*)d_in[5];
    const float* weight = (const float*)d_in[6];
    const float* bias   = (const float*)d_in[7];
    float* out = (float*)d_out;

    // Stage 0: merged transpose + prepack
    prep_kernel<<<NT_BLOCKS + NP_BLOCKS, 256>>>(ref, nbr, off_w, mask_w, weight);

    // Stage 1: conv
    {
        cudaFuncSetAttribute(conv_mma_kernel,
                             cudaFuncAttributeMaxDynamicSharedMemorySize, SMEM_TOT);
        dim3 grid(WW / 16, HH / 8, BB * 2);
        conv_mma_kernel<<<grid, 256, SMEM_TOT>>>(off_b, mask_b);
    }
    // Stage 2: sampling + einsum
    {
        cudaFuncSetAttribute(samp_einsum_kernel,
                             cudaFuncAttributeMaxDynamicSharedMemorySize, SMEM_SAMP);
        dim3 grid(WW / 16, HH / 8, BB);
        samp_einsum_kernel<<<grid, 256, SMEM_SAMP>>>(bias, out);
    }
}